// round 9
// baseline (speedup 1.0000x reference)
#include <cuda_runtime.h>
#include <cstdint>

// LinearReg: sum over rows/groups of L2 norms of 25-element groups of
// weight[N,800] f32, /N, * 0.001 * c_omega.
// R5 champion structure (TMA producer warp + 4-stage ring, 25.6KB chunks,
// 2 blocks/SM) with row-balanced contiguous per-block partition
// (imbalance quantum 1 row instead of 8) and relaxed producer waits.

#define GROUPS 32
#define GSIZE 25
#define ROW_ELEMS 800
#define RPB 8                                    // rows per chunk
#define STAGES 4
#define CWARPS 8
#define CONSUMERS (CWARPS * 32)                  // 256
#define THREADS (CONSUMERS + 32)                 // + producer warp = 288
#define CHUNK_FLOATS (RPB * ROW_ELEMS)           // 6400
#define CHUNK_BYTES (CHUNK_FLOATS * 4)           // 25600
#define SMEM_BYTES (STAGES * CHUNK_BYTES)        // 102400 -> 2 blocks/SM
#define MAXBLOCKS 4096

__device__ float g_partials[MAXBLOCKS];
__device__ unsigned g_count = 0;   // last block resets -> replay-deterministic

#define MBAR_INIT(addr, cnt) \
    asm volatile("mbarrier.init.shared.b64 [%0], %1;" :: "r"(addr), "r"(cnt) : "memory")
#define MBAR_ARRIVE(addr) \
    asm volatile("mbarrier.arrive.shared.b64 _, [%0];" :: "r"(addr) : "memory")
#define MBAR_EXPECT_TX(addr, bytes) \
    asm volatile("mbarrier.arrive.expect_tx.shared.b64 _, [%0], %1;" \
                 :: "r"(addr), "r"(bytes) : "memory")
// Acquire wait: consumers (generic LDS follows).
#define MBAR_WAIT(addr, parity) do {                                          \
    asm volatile(                                                             \
        "{\n\t"                                                               \
        ".reg .pred P;\n\t"                                                   \
        "WAIT_%=:\n\t"                                                        \
        "mbarrier.try_wait.parity.acquire.cta.shared::cta.b64 P, [%0], %1, 0x989680;\n\t" \
        "@P bra DONE_%=;\n\t"                                                 \
        "bra WAIT_%=;\n\t"                                                    \
        "DONE_%=:\n\t"                                                        \
        "}" :: "r"(addr), "r"(parity) : "memory");                            \
} while (0)
// Relaxed wait: producer only (post-wait access is async-proxy TMA).
#define MBAR_WAIT_RELAXED(addr, parity) do {                                  \
    asm volatile(                                                             \
        "{\n\t"                                                               \
        ".reg .pred P;\n\t"                                                   \
        "WAIT_%=:\n\t"                                                        \
        "mbarrier.try_wait.parity.relaxed.cta.shared::cta.b64 P, [%0], %1, 0x989680;\n\t" \
        "@P bra DONE_%=;\n\t"                                                 \
        "bra WAIT_%=;\n\t"                                                    \
        "DONE_%=:\n\t"                                                        \
        "}" :: "r"(addr), "r"(parity) : "memory");                            \
} while (0)

__device__ __forceinline__ void tma_bulk_1d(uint32_t sdst, const void* gsrc,
                                            uint32_t bytes, uint32_t mbar) {
    asm volatile(
        "cp.async.bulk.shared::cluster.global.mbarrier::complete_tx::bytes "
        "[%0], [%1], %2, [%3];"
        :: "r"(sdst), "l"(__cvta_generic_to_global(gsrc)), "r"(bytes), "r"(mbar)
        : "memory");
}

__global__ __launch_bounds__(THREADS) void lr_fused_kernel(
    const float* __restrict__ w, const unsigned* __restrict__ c_omega_raw,
    float* __restrict__ out, int n)
{
    extern __shared__ float s[];                 // [STAGES][CHUNK_FLOATS]
    __shared__ __align__(8) unsigned long long mbar_full[STAGES];
    __shared__ __align__(8) unsigned long long mbar_empty[STAGES];
    __shared__ float warpsum[THREADS / 32];
    __shared__ double warpsumd[THREADS / 32];
    __shared__ int is_last;

    const uint32_t sbase = (uint32_t)__cvta_generic_to_shared(s);
    const uint32_t full0  = (uint32_t)__cvta_generic_to_shared(mbar_full);
    const uint32_t empty0 = (uint32_t)__cvta_generic_to_shared(mbar_empty);

    // Row-balanced contiguous partition: block gets base or base+1 rows.
    const int G = gridDim.x;
    const int base = n / G, rem = n % G;
    const int b = blockIdx.x;
    const int rstart = b * base + (b < rem ? b : rem);
    const int rcnt = base + (b < rem ? 1 : 0);
    const int nlocal = (rcnt + RPB - 1) / RPB;   // local chunk count

    if (threadIdx.x == 0) {
        #pragma unroll
        for (int i = 0; i < STAGES; i++) {
            MBAR_INIT(full0 + i * 8, 1);            // completed by TMA tx
            MBAR_INIT(empty0 + i * 8, CONSUMERS);   // per-thread arrives (R5)
        }
        asm volatile("fence.proxy.async.shared::cta;" ::: "memory");
    }
    __syncthreads();

    float total = 0.0f;

    if (threadIdx.x >= CONSUMERS) {
        // ---- producer warp (one elected thread issues TMA) ----
        if (threadIdx.x == CONSUMERS) {
            int st = 0, ph = 1;                     // first empty-waits pass
            for (int c = 0; c < nlocal; c++) {
                MBAR_WAIT_RELAXED(empty0 + st * 8, (uint32_t)ph);
                int rowbase = rstart + c * RPB;
                int rows = rcnt - c * RPB;
                if (rows > RPB) rows = RPB;
                uint32_t bytes = (uint32_t)rows * ROW_ELEMS * 4;
                uint32_t fb = full0 + st * 8;
                MBAR_EXPECT_TX(fb, bytes);
                tma_bulk_1d(sbase + st * CHUNK_BYTES,
                            w + (long long)rowbase * ROW_ELEMS, bytes, fb);
                if (++st == STAGES) { st = 0; ph ^= 1; }
            }
        }
    } else {
        // ---- consumer warps: row = warp (8 rows), group = lane ----
        // lane offsets l*25 mod 32 form a permutation -> conflict-free LDS.
        const int row = threadIdx.x >> 5;
        const int grp = threadIdx.x & 31;
        int st = 0, ph = 0;
        for (int c = 0; c < nlocal; c++) {
            MBAR_WAIT(full0 + st * 8, (uint32_t)ph);
            int rows = rcnt - c * RPB;
            if (rows > RPB) rows = RPB;
            if (row < rows) {
                const float* p = s + st * CHUNK_FLOATS + row * ROW_ELEMS
                               + grp * GSIZE;
                float acc = 0.0f;
                #pragma unroll
                for (int i = 0; i < GSIZE; i++)
                    acc = fmaf(p[i], p[i], acc);
                total += sqrtf(acc);
            }
            MBAR_ARRIVE(empty0 + st * 8);
            if (++st == STAGES) { st = 0; ph ^= 1; }
        }
    }
    __syncthreads();   // everyone done; every issued TMA was consumed

    // ---- block reduction over all 9 warps (producer contributes 0) ----
    #pragma unroll
    for (int o = 16; o > 0; o >>= 1)
        total += __shfl_xor_sync(0xffffffffu, total, o);
    if ((threadIdx.x & 31) == 0)
        warpsum[threadIdx.x >> 5] = total;
    __syncthreads();

    if (threadIdx.x == 0) {
        float bsum = 0.0f;
        #pragma unroll
        for (int i = 0; i < THREADS / 32; i++)
            bsum += warpsum[i];
        g_partials[blockIdx.x] = bsum;
        __threadfence();                            // publish before ticket
        unsigned t = atomicAdd(&g_count, 1u);
        is_last = (t == gridDim.x - 1);
    }
    __syncthreads();

    if (is_last) {
        double v = 0.0;
        for (int i = threadIdx.x; i < (int)gridDim.x; i += THREADS)
            v += (double)__ldcg(&g_partials[i]);    // bypass L1
        #pragma unroll
        for (int o = 16; o > 0; o >>= 1)
            v += __shfl_xor_sync(0xffffffffu, v, o);
        if ((threadIdx.x & 31) == 0)
            warpsumd[threadIdx.x >> 5] = v;
        __syncthreads();
        if (threadIdx.x == 0) {
            double sum = 0.0;
            #pragma unroll
            for (int i = 0; i < THREADS / 32; i++)
                sum += warpsumd[i];
            // c_omega is python int 1; accept int-typed or f32-typed scalar
            // deterministically by bit-pattern magnitude.
            unsigned u = *c_omega_raw;
            float c = (u < (1u << 30)) ? (float)(int)u : __uint_as_float(u);
            out[0] = (float)(sum / (double)n * 0.001 * (double)c);
            g_count = 0;                            // restore for graph replay
        }
    }
}

extern "C" void kernel_launch(void* const* d_in, const int* in_sizes, int n_in,
                              void* d_out, int out_size)
{
    const float* w = (const float*)d_in[0];
    const unsigned* c_omega = (const unsigned*)d_in[1];
    int n = in_sizes[0] / (GROUPS * GSIZE);   // 100000

    cudaFuncSetAttribute(lr_fused_kernel,
                         cudaFuncAttributeMaxDynamicSharedMemorySize, SMEM_BYTES);

    int blocks = 152 * 2;                      // 2 blocks/SM, 102.4KB smem each
    if (blocks > n) blocks = n;                // degenerate-safety
    if (blocks > MAXBLOCKS) blocks = MAXBLOCKS;

    lr_fused_kernel<<<blocks, THREADS, SMEM_BYTES>>>(w, c_omega, (float*)d_out, n);
}

// round 10
// speedup vs baseline: 1.0446x; 1.0446x over previous
#include <cuda_runtime.h>
#include <cstdint>

// LinearReg: sum over rows/groups of L2 norms of 25-element groups of
// weight[N,800] f32, /N, * 0.001 * c_omega.
// R5 champion (TMA producer warp + 4-stage mbarrier ring, 25.6KB chunks,
// strided chunk assignment) with a zero-tail grid: 250 blocks x exactly
// 50 chunks. Decoupled last-block reduction.

#define GROUPS 32
#define GSIZE 25
#define ROW_ELEMS 800
#define RPB 8                                    // rows per chunk
#define STAGES 4
#define CWARPS 8
#define CONSUMERS (CWARPS * 32)                  // 256
#define THREADS (CONSUMERS + 32)                 // + producer warp = 288
#define CHUNK_FLOATS (RPB * ROW_ELEMS)           // 6400
#define CHUNK_BYTES (CHUNK_FLOATS * 4)           // 25600
#define SMEM_BYTES (STAGES * CHUNK_BYTES)        // 102400 -> <=2 blocks/SM
#define MAXBLOCKS 4096

__device__ float g_partials[MAXBLOCKS];
__device__ unsigned g_count = 0;   // last block resets -> replay-deterministic

#define MBAR_INIT(addr, cnt) \
    asm volatile("mbarrier.init.shared.b64 [%0], %1;" :: "r"(addr), "r"(cnt) : "memory")
#define MBAR_ARRIVE(addr) \
    asm volatile("mbarrier.arrive.shared.b64 _, [%0];" :: "r"(addr) : "memory")
#define MBAR_EXPECT_TX(addr, bytes) \
    asm volatile("mbarrier.arrive.expect_tx.shared.b64 _, [%0], %1;" \
                 :: "r"(addr), "r"(bytes) : "memory")
#define MBAR_WAIT(addr, parity) do {                                          \
    asm volatile(                                                             \
        "{\n\t"                                                               \
        ".reg .pred P;\n\t"                                                   \
        "WAIT_%=:\n\t"                                                        \
        "mbarrier.try_wait.parity.acquire.cta.shared::cta.b64 P, [%0], %1, 0x989680;\n\t" \
        "@P bra DONE_%=;\n\t"                                                 \
        "bra WAIT_%=;\n\t"                                                    \
        "DONE_%=:\n\t"                                                        \
        "}" :: "r"(addr), "r"(parity) : "memory");                            \
} while (0)

__device__ __forceinline__ void tma_bulk_1d(uint32_t sdst, const void* gsrc,
                                            uint32_t bytes, uint32_t mbar) {
    asm volatile(
        "cp.async.bulk.shared::cluster.global.mbarrier::complete_tx::bytes "
        "[%0], [%1], %2, [%3];"
        :: "r"(sdst), "l"(__cvta_generic_to_global(gsrc)), "r"(bytes), "r"(mbar)
        : "memory");
}

__global__ __launch_bounds__(THREADS) void lr_fused_kernel(
    const float* __restrict__ w, const unsigned* __restrict__ c_omega_raw,
    float* __restrict__ out, int n)
{
    extern __shared__ float s[];                 // [STAGES][CHUNK_FLOATS]
    __shared__ __align__(8) unsigned long long mbar_full[STAGES];
    __shared__ __align__(8) unsigned long long mbar_empty[STAGES];
    __shared__ float warpsum[THREADS / 32];
    __shared__ double warpsumd[THREADS / 32];
    __shared__ int is_last;

    const int nchunks = (n + RPB - 1) / RPB;
    const uint32_t sbase = (uint32_t)__cvta_generic_to_shared(s);
    const uint32_t full0  = (uint32_t)__cvta_generic_to_shared(mbar_full);
    const uint32_t empty0 = (uint32_t)__cvta_generic_to_shared(mbar_empty);
    const int G = gridDim.x;

    if (threadIdx.x == 0) {
        #pragma unroll
        for (int i = 0; i < STAGES; i++) {
            MBAR_INIT(full0 + i * 8, 1);           // completed by TMA tx
            MBAR_INIT(empty0 + i * 8, CONSUMERS);  // all consumers arrive
        }
        asm volatile("fence.proxy.async.shared::cta;" ::: "memory");
    }
    __syncthreads();

    float total = 0.0f;

    if (threadIdx.x >= CONSUMERS) {
        // ---- producer warp (one elected thread issues TMA) ----
        if (threadIdx.x == CONSUMERS) {
            int st = 0, ph = 1;                    // first empty-waits pass
            for (int chunk = blockIdx.x; chunk < nchunks; chunk += G) {
                MBAR_WAIT(empty0 + st * 8, (uint32_t)ph);
                int rows = n - chunk * RPB;
                if (rows > RPB) rows = RPB;
                uint32_t bytes = (uint32_t)rows * ROW_ELEMS * 4;
                uint32_t fb = full0 + st * 8;
                MBAR_EXPECT_TX(fb, bytes);
                tma_bulk_1d(sbase + st * CHUNK_BYTES,
                            w + (long long)chunk * CHUNK_FLOATS, bytes, fb);
                if (++st == STAGES) { st = 0; ph ^= 1; }
            }
        }
    } else {
        // ---- consumer warps: row = warp (8 rows), group = lane ----
        // lane offsets l*25 mod 32 form a permutation -> conflict-free LDS.
        const int row = threadIdx.x >> 5;
        const int grp = threadIdx.x & 31;
        int st = 0, ph = 0;
        for (int chunk = blockIdx.x; chunk < nchunks; chunk += G) {
            MBAR_WAIT(full0 + st * 8, (uint32_t)ph);
            int rows = n - chunk * RPB;
            if (rows > RPB) rows = RPB;
            if (row < rows) {
                const float* p = s + st * CHUNK_FLOATS + row * ROW_ELEMS
                               + grp * GSIZE;
                float acc = 0.0f;
                #pragma unroll
                for (int i = 0; i < GSIZE; i++)
                    acc = fmaf(p[i], p[i], acc);
                total += sqrtf(acc);
            }
            MBAR_ARRIVE(empty0 + st * 8);
            if (++st == STAGES) { st = 0; ph ^= 1; }
        }
    }
    __syncthreads();   // everyone done; every issued TMA was consumed

    // ---- block reduction over all 9 warps (producer contributes 0) ----
    #pragma unroll
    for (int o = 16; o > 0; o >>= 1)
        total += __shfl_xor_sync(0xffffffffu, total, o);
    if ((threadIdx.x & 31) == 0)
        warpsum[threadIdx.x >> 5] = total;
    __syncthreads();

    if (threadIdx.x == 0) {
        float bsum = 0.0f;
        #pragma unroll
        for (int i = 0; i < THREADS / 32; i++)
            bsum += warpsum[i];
        g_partials[blockIdx.x] = bsum;
        __threadfence();                          // publish partial before ticket
        unsigned t = atomicAdd(&g_count, 1u);
        is_last = (t == gridDim.x - 1);
    }
    __syncthreads();

    if (is_last) {
        double v = 0.0;
        for (int i = threadIdx.x; i < (int)gridDim.x; i += THREADS)
            v += (double)__ldcg(&g_partials[i]);     // bypass L1
        #pragma unroll
        for (int o = 16; o > 0; o >>= 1)
            v += __shfl_xor_sync(0xffffffffu, v, o);
        if ((threadIdx.x & 31) == 0)
            warpsumd[threadIdx.x >> 5] = v;
        __syncthreads();
        if (threadIdx.x == 0) {
            double sum = 0.0;
            #pragma unroll
            for (int i = 0; i < THREADS / 32; i++)
                sum += warpsumd[i];
            // c_omega is python int 1; accept int-typed or f32-typed scalar
            // deterministically by bit-pattern magnitude.
            unsigned u = *c_omega_raw;
            float c = (u < (1u << 30)) ? (float)(int)u : __uint_as_float(u);
            out[0] = (float)(sum / (double)n * 0.001 * (double)c);
            g_count = 0;                          // restore for next graph replay
        }
    }
}

extern "C" void kernel_launch(void* const* d_in, const int* in_sizes, int n_in,
                              void* d_out, int out_size)
{
    const float* w = (const float*)d_in[0];
    const unsigned* c_omega = (const unsigned*)d_in[1];
    int n = in_sizes[0] / (GROUPS * GSIZE);   // 100000

    cudaFuncSetAttribute(lr_fused_kernel,
                         cudaFuncAttributeMaxDynamicSharedMemorySize, SMEM_BYTES);

    int nchunks = (n + RPB - 1) / RPB;         // 12500
    // Zero-tail grid: pick the largest G <= 304 (2 blocks/SM cap) that
    // divides nchunks exactly; for 12500 that's 250 (50 chunks/block).
    int blocks = 304;
    for (int g = 304; g >= 152; g--) {
        if (nchunks % g == 0) { blocks = g; break; }
    }
    if (blocks > nchunks) blocks = nchunks;
    if (blocks > MAXBLOCKS) blocks = MAXBLOCKS;

    lr_fused_kernel<<<blocks, THREADS, SMEM_BYTES>>>(w, c_omega, (float*)d_out, n);
}